// round 8
// baseline (speedup 1.0000x reference)
#include <cuda_runtime.h>
#include <cuda_bf16.h>
#include <cstdint>

// Problem dims
#define TT   512
#define BB   64
#define II   512
#define HH   512
#define G4   2048          // 4*H gate rows
#define NCTA 128           // persistent CTAs for recurrence

// Phase A GEMM tiling (mma.sync bf16, base-target PTX only — NO tcgen05)
#define KCH     32                  // k elems per chunk
#define NCHK    (II / KCH)          // 16 chunks
#define SROW    40                  // padded smem row (elems): 80B, conflict-free
#define TILEB   (128 * SROW * 2)    // 10240 B per matrix tile
#define STAGEB  (4 * TILEB)         // A_hi|A_lo|B_hi|B_lo = 40960 B
#define SMEM_A_TOT (2 * STAGEB)     // 81920 B double-buffered

typedef unsigned long long u64;

// ---------------------------------------------------------------------------
// Global scratch (static __device__ arrays — no allocation allowed)
// ---------------------------------------------------------------------------
__device__ float g_xp[(size_t)TT * G4 * BB];        // x_proj [t][g][b]
__device__ float g_h[2][HH * BB];                   // h double buffer [j][b]
__device__ __nv_bfloat16 g_in_hi[(size_t)TT * BB * II];
__device__ __nv_bfloat16 g_in_lo[(size_t)TT * BB * II];
__device__ __nv_bfloat16 g_w_hi[(size_t)G4 * II];
__device__ __nv_bfloat16 g_w_lo[(size_t)G4 * II];
__device__ unsigned int          g_bar_cnt;
__device__ volatile unsigned int g_bar_gen;

// ---------------------------------------------------------------------------
// PTX helpers (base-target features only)
// ---------------------------------------------------------------------------
__device__ __forceinline__ uint32_t smem_u32(const void* p) {
    uint32_t a;
    asm("{ .reg .u64 t; cvta.to.shared.u64 t, %1; cvt.u32.u64 %0, t; }"
        : "=r"(a) : "l"(p));
    return a;
}
__device__ __forceinline__ void mbar_init(uint32_t addr, uint32_t count) {
    asm volatile("mbarrier.init.shared.b64 [%0], %1;" :: "r"(addr), "r"(count) : "memory");
}
__device__ __forceinline__ void mbar_expect_tx(uint32_t addr, uint32_t bytes) {
    asm volatile("mbarrier.arrive.expect_tx.shared.b64 _, [%0], %1;"
                 :: "r"(addr), "r"(bytes) : "memory");
}
__device__ __forceinline__ void mbar_wait(uint32_t addr, uint32_t parity) {
    asm volatile(
        "{\n\t"
        ".reg .pred P1;\n\t"
        "LAB_WAIT%=:\n\t"
        "mbarrier.try_wait.parity.acquire.cta.shared::cta.b64 P1, [%0], %1, 0x989680;\n\t"
        "@P1 bra LAB_DONE%=;\n\t"
        "bra LAB_WAIT%=;\n\t"
        "LAB_DONE%=:\n\t"
        "}"
        :: "r"(addr), "r"(parity) : "memory");
}
__device__ __forceinline__ void bulk_g2s(uint32_t dst, const float* src,
                                         uint32_t bytes, uint32_t mbar) {
    asm volatile(
        "cp.async.bulk.shared::cluster.global.mbarrier::complete_tx::bytes [%0], [%1], %2, [%3];"
        :: "r"(dst), "l"(src), "r"(bytes), "r"(mbar) : "memory");
}
__device__ __forceinline__ void fence_proxy_async_cta() {
    asm volatile("fence.proxy.async.shared::cta;" ::: "memory");
}
__device__ __forceinline__ void cpasync16(uint32_t dst, const void* src) {
    asm volatile("cp.async.cg.shared.global [%0], [%1], 16;"
                 :: "r"(dst), "l"(src) : "memory");
}
__device__ __forceinline__ void cp_commit() {
    asm volatile("cp.async.commit_group;" ::: "memory");
}
__device__ __forceinline__ void ldsm4(uint32_t* r, uint32_t addr) {
    asm volatile("ldmatrix.sync.aligned.m8n8.x4.shared.b16 {%0,%1,%2,%3}, [%4];"
                 : "=r"(r[0]), "=r"(r[1]), "=r"(r[2]), "=r"(r[3]) : "r"(addr));
}
__device__ __forceinline__ void mma16816(float* d, const uint32_t* a, const uint32_t* b) {
    asm volatile(
        "mma.sync.aligned.m16n8k16.row.col.f32.bf16.bf16.f32 "
        "{%0,%1,%2,%3}, {%4,%5,%6,%7}, {%8,%9}, {%0,%1,%2,%3};"
        : "+f"(d[0]), "+f"(d[1]), "+f"(d[2]), "+f"(d[3])
        : "r"(a[0]), "r"(a[1]), "r"(a[2]), "r"(a[3]), "r"(b[0]), "r"(b[1]));
}
// packed f32x2 FMA (PTX >=8.6, sm_100+ base target): acc = w*h + acc, lanewise fp32
__device__ __forceinline__ void ffma2(u64& acc, u64 w, u64 h) {
    asm("fma.rn.f32x2 %0, %1, %2, %0;" : "+l"(acc) : "l"(w), "l"(h));
}
__device__ __forceinline__ u64 lds64(uint32_t addr) {
    u64 v;
    asm volatile("ld.shared.b64 %0, [%1];" : "=l"(v) : "r"(addr));
    return v;
}
__device__ __forceinline__ void lds_v2_64(u64& a, u64& b, uint32_t addr) {
    asm volatile("ld.shared.v2.b64 {%0,%1}, [%2];" : "=l"(a), "=l"(b) : "r"(addr));
}

__device__ __forceinline__ float sigf(float x) { return 1.0f / (1.0f + __expf(-x)); }
__device__ __forceinline__ float tanh_fast(float x) {
    return 1.0f - 2.0f / (1.0f + __expf(2.0f * x));
}

// release/acquire software grid barrier (all NCTA CTAs resident)
__device__ __forceinline__ void grid_barrier() {
    __syncthreads();
    if (threadIdx.x == 0) {
        __threadfence();
        unsigned old = g_bar_gen;
        if (atomicAdd(&g_bar_cnt, 1u) == NCTA - 1u) {
            g_bar_cnt = 0;
            __threadfence();
            g_bar_gen = old + 1u;
        } else {
            while (g_bar_gen == old) { }
        }
        __threadfence();
    }
    __syncthreads();
}

// ---------------------------------------------------------------------------
// Init: barrier reset + h0 transpose
// ---------------------------------------------------------------------------
__global__ void init_state(const float* __restrict__ h0) {
    int i = blockIdx.x * blockDim.x + threadIdx.x;
    if (i == 0) { g_bar_cnt = 0; g_bar_gen = 0; }
    if (i < HH * BB) {
        int j = i >> 6, b = i & 63;
        g_h[0][i] = h0[b * HH + j];
    }
}

// ---------------------------------------------------------------------------
// Split fp32 -> bf16 hi/lo for input and W_ih
// ---------------------------------------------------------------------------
__global__ void convert_split(const float* __restrict__ input,
                              const float* __restrict__ W_ih) {
    const size_t n_in = (size_t)TT * BB * II;
    const size_t n_w  = (size_t)G4 * II;
    size_t stride = (size_t)gridDim.x * blockDim.x;
    for (size_t i = blockIdx.x * (size_t)blockDim.x + threadIdx.x; i < n_in; i += stride) {
        float x = input[i];
        __nv_bfloat16 h = __float2bfloat16(x);
        g_in_hi[i] = h;
        g_in_lo[i] = __float2bfloat16(x - __bfloat162float(h));
    }
    for (size_t i = blockIdx.x * (size_t)blockDim.x + threadIdx.x; i < n_w; i += stride) {
        float x = W_ih[i];
        __nv_bfloat16 h = __float2bfloat16(x);
        g_w_hi[i] = h;
        g_w_lo[i] = __float2bfloat16(x - __bfloat162float(h));
    }
}

// ---------------------------------------------------------------------------
// Phase A: x_proj via mma.sync bf16 split GEMM (3 passes: hh + hl + lh).
// (unchanged from R6 — passing, ~1.3-1.4ms; Round-7 target)
// ---------------------------------------------------------------------------
__device__ __forceinline__ void load_chunk_a(int c, int stage, int mbase, int nbase,
                                             uint32_t sbase) {
    const int tid = threadIdx.x;
    const uint32_t st = sbase + (uint32_t)stage * STAGEB;
    #pragma unroll
    for (int it = 0; it < 8; ++it) {
        int i = tid + it * 256;
        int which = i >> 10;            // 0 = A(W), 1 = B(X)
        int rem   = i & 1023;
        int hl    = (rem >> 9) & 1;     // 0 = hi, 1 = lo
        int r     = (rem >> 2) & 127;
        int cc    = rem & 3;            // 8-elem (16B) column chunk
        const __nv_bfloat16* gsrc =
            which ? (hl ? g_in_lo : g_in_hi) : (hl ? g_w_lo : g_w_hi);
        int grow = which ? (nbase + r) : (mbase + r);
        const void* src = gsrc + (size_t)grow * II + c * KCH + cc * 8;
        uint32_t dst = st + (uint32_t)which * (2 * TILEB) + (uint32_t)hl * TILEB
                     + (uint32_t)(r * (SROW * 2) + cc * 16);
        cpasync16(dst, src);
    }
    cp_commit();
}

__global__ void __launch_bounds__(256, 2)
xproj_mma(const float* __restrict__ b_ih, const float* __restrict__ b_hh) {
    extern __shared__ char dsm[];
    const uint32_t sbase = smem_u32(dsm);

    const int tid  = threadIdx.x;
    const int wid  = tid >> 5;
    const int lane = tid & 31;
    const int mbase = blockIdx.x * 128;   // g
    const int nbase = blockIdx.y * 128;   // tb
    const int wm = (wid >> 2) * 64;
    const int wn = (wid & 3) * 32;

    uint32_t aoff[4], boff[2];
    {
        int l15 = lane & 15, lhi = lane >> 4;
        #pragma unroll
        for (int f = 0; f < 4; ++f)
            aoff[f] = (uint32_t)(((wm + f * 16 + l15) * SROW + lhi * 8) * 2);
        int sub = lane & 7, grp = lane >> 3;
        #pragma unroll
        for (int p = 0; p < 2; ++p)
            boff[p] = (uint32_t)(((wn + p * 16 + (grp >> 1) * 8 + sub) * SROW
                                  + (grp & 1) * 8) * 2);
    }

    float acc[4][4][4];
    #pragma unroll
    for (int f = 0; f < 4; ++f)
        #pragma unroll
        for (int n = 0; n < 4; ++n)
            #pragma unroll
            for (int e = 0; e < 4; ++e) acc[f][n][e] = 0.0f;

    load_chunk_a(0, 0, mbase, nbase, sbase);
    load_chunk_a(1, 1, mbase, nbase, sbase);

    for (int c = 0; c < NCHK; ++c) {
        if (c < NCHK - 1) asm volatile("cp.async.wait_group 1;" ::: "memory");
        else              asm volatile("cp.async.wait_group 0;" ::: "memory");
        __syncthreads();

        const uint32_t st = sbase + (uint32_t)(c & 1) * STAGEB;
        const uint32_t Ah = st, Al = st + TILEB, Bh = st + 2 * TILEB, Bl = st + 3 * TILEB;

        #pragma unroll
        for (int step = 0; step < 2; ++step) {
            const uint32_t ko = (uint32_t)step * 32;
            uint32_t ah[16], bh[8], bl[8];
            #pragma unroll
            for (int f = 0; f < 4; ++f) ldsm4(&ah[f * 4], Ah + aoff[f] + ko);
            #pragma unroll
            for (int p = 0; p < 2; ++p) {
                ldsm4(&bh[p * 4], Bh + boff[p] + ko);
                ldsm4(&bl[p * 4], Bl + boff[p] + ko);
            }
            #pragma unroll
            for (int f = 0; f < 4; ++f)
                #pragma unroll
                for (int n = 0; n < 4; ++n) {
                    mma16816(acc[f][n], &ah[f * 4], &bh[n * 2]);
                    mma16816(acc[f][n], &ah[f * 4], &bl[n * 2]);
                }
            uint32_t al[16];
            #pragma unroll
            for (int f = 0; f < 4; ++f) ldsm4(&al[f * 4], Al + aoff[f] + ko);
            #pragma unroll
            for (int f = 0; f < 4; ++f)
                #pragma unroll
                for (int n = 0; n < 4; ++n)
                    mma16816(acc[f][n], &al[f * 4], &bh[n * 2]);
        }
        __syncthreads();
        if (c + 2 < NCHK) load_chunk_a(c + 2, (c & 1), mbase, nbase, sbase);
    }

    const int rrow = lane >> 2;
    const int ncol = (lane & 3) * 2;
    #pragma unroll
    for (int f = 0; f < 4; ++f) {
        const int g0 = mbase + wm + f * 16 + rrow;
        const float bias0 = b_ih[g0] + b_hh[g0];
        const float bias1 = b_ih[g0 + 8] + b_hh[g0 + 8];
        #pragma unroll
        for (int n = 0; n < 4; ++n) {
            const int tb = nbase + wn + n * 8 + ncol;
            const int t  = tb >> 6;
            const int b  = tb & 63;
            float* base = g_xp + (size_t)t * (G4 * BB) + b;
            float2 v0 = make_float2(acc[f][n][0] + bias0, acc[f][n][1] + bias0);
            float2 v1 = make_float2(acc[f][n][2] + bias1, acc[f][n][3] + bias1);
            *(float2*)(base + (size_t)g0 * 64)       = v0;
            *(float2*)(base + (size_t)(g0 + 8) * 64) = v1;
        }
    }
}

// ---------------------------------------------------------------------------
// Phase B v2: persistent reverse recurrence with packed f32x2 FMA.
// CTA owns 16 gate rows (4 gates x 4 j). Thread (r2=tid>>5, b2=tid&31) owns
// rows {2r2, 2r2+1} x batches {2b2, 2b2+1} as two f32x2 accumulators.
// Shared: hs[512][64] fp32 128K | ws_dup[512][16][(w,w)] 64K | gsh[16][64] 4K
// ---------------------------------------------------------------------------
#define SM_HS   0
#define SM_WS   131072
#define SM_GSH  (131072 + 65536)
#define SM_MBAR (SM_GSH + 4096)
#define SM_TOT  (SM_MBAR + 64)

__global__ void __launch_bounds__(256, 1)
lstm_recurrent(const float* __restrict__ W_hh,
               const float* __restrict__ c0,
               float* __restrict__ out)
{
    extern __shared__ char smem[];
    float* wsd = (float*)(smem + SM_WS);
    float* gsh = (float*)(smem + SM_GSH);
    const uint32_t hs_u32 = smem_u32(smem + SM_HS);
    const uint32_t ws_u32 = smem_u32(smem + SM_WS);
    const uint32_t gs_u32 = smem_u32(smem + SM_GSH);
    const uint32_t mbar0  = smem_u32(smem + SM_MBAR);

    const int tid   = threadIdx.x;
    const int cta   = blockIdx.x;
    const int jbase = cta * 4;

    // Build ws_dup: [k][16 local rows][(w,w)]; local row r = q*4+jj <-> global
    // row q*512 + jbase + jj.  (coalesced LDG over k; smem scatter is cheap)
    for (int idx = tid; idx < 16 * 512; idx += 256) {
        int r = idx >> 9, k = idx & 511;
        int grow = (r >> 2) * 512 + jbase + (r & 3);
        float w = W_hh[(size_t)grow * HH + k];
        wsd[(k * 16 + r) * 2 + 0] = w;
        wsd[(k * 16 + r) * 2 + 1] = w;
    }

    // update-role mapping + c state
    const int b_u = tid & 63, jj_u = tid >> 6;
    float c_reg = c0[b_u * HH + jbase + jj_u];

    if (tid == 0) {
        #pragma unroll
        for (int i = 0; i < 4; ++i) mbar_init(mbar0 + 8 * i, 1);
    }
    fence_proxy_async_cta();
    __syncthreads();

    // gemm-role mapping
    const int r2 = tid >> 5;            // 0..7 -> rows 2r2, 2r2+1
    const int b2 = tid & 31;            // -> batches 2b2, 2b2+1
    const int row0 = 2 * r2, row1 = 2 * r2 + 1;
    const int gg0 = (row0 >> 2) * 512 + jbase + (row0 & 3);  // global gate rows
    const int gg1 = (row1 >> 2) * 512 + jbase + (row1 & 3);

    for (int s = 0; s < TT; ++s) {
        const int t   = TT - 1 - s;
        const int cur = s & 1;
        const uint32_t phase = (uint32_t)(s & 1);

        // stage h into shared: 4 pipelined 32KB bulk copies
        if (tid == 0) {
            fence_proxy_async_cta();
            const float* src = g_h[cur];
            #pragma unroll
            for (int ch = 0; ch < 4; ++ch) {
                mbar_expect_tx(mbar0 + 8 * ch, 32768u);
                bulk_g2s(hs_u32 + (uint32_t)ch * 32768u, src + ch * 8192,
                         32768u, mbar0 + 8 * ch);
            }
        }

        // accumulators seeded from x_proj (b-adjacent pair = f32x2 lanes)
        const float* xp = g_xp + (size_t)t * (G4 * BB);
        u64 acc0 = *(const u64*)(xp + (size_t)gg0 * 64 + 2 * b2);
        u64 acc1 = *(const u64*)(xp + (size_t)gg1 * 64 + 2 * b2);

        #pragma unroll 1
        for (int ch = 0; ch < 4; ++ch) {
            mbar_wait(mbar0 + 8 * ch, phase);
            uint32_t ha = hs_u32 + (uint32_t)ch * 32768u + (uint32_t)b2 * 8u;
            uint32_t wa = ws_u32 + (uint32_t)ch * 16384u + (uint32_t)r2 * 16u;
            #pragma unroll 8
            for (int kk = 0; kk < 128; ++kk) {
                u64 hh = lds64(ha);
                u64 w0, w1;
                lds_v2_64(w0, w1, wa);
                ffma2(acc0, w0, hh);
                ffma2(acc1, w1, hh);
                ha += 256u;   // next k: 64 floats
                wa += 128u;   // next k: 16 pairs
            }
        }

        // gates -> shared (store packed pairs directly)
        {
            uint32_t ga = gs_u32 + (uint32_t)(row0 * 64 + 2 * b2) * 4u;
            asm volatile("st.shared.b64 [%0], %1;" :: "r"(ga), "l"(acc0) : "memory");
            asm volatile("st.shared.b64 [%0], %1;" :: "r"(ga + 256u), "l"(acc1) : "memory");
        }
        __syncthreads();

        // elementwise LSTM cell update: thread owns (b_u, j = jbase+jj_u)
        float gi = gsh[( 0 + jj_u) * 64 + b_u];
        float gf = gsh[( 4 + jj_u) * 64 + b_u];
        float gg = gsh[( 8 + jj_u) * 64 + b_u];
        float go = gsh[(12 + jj_u) * 64 + b_u];

        float ig = sigf(gi), fg = sigf(gf), og = sigf(go);
        c_reg = fg * c_reg + ig * tanh_fast(gg);
        float hn = og * tanh_fast(c_reg);

        const int jg = jbase + jj_u;
        g_h[cur ^ 1][jg * 64 + b_u] = hn;
        out[(size_t)t * (BB * HH) + (size_t)b_u * HH + jg] = hn;
        if (s == TT - 1) {
            out[(size_t)TT * (BB * HH) + (size_t)b_u * HH + jg]           = hn;
            out[(size_t)TT * (BB * HH) + BB * HH + (size_t)b_u * HH + jg] = c_reg;
        }

        grid_barrier();   // release h writes; also fences smem reuse + mbar phase
    }
}

// ---------------------------------------------------------------------------
// Launch
// ---------------------------------------------------------------------------
extern "C" void kernel_launch(void* const* d_in, const int* in_sizes, int n_in,
                              void* d_out, int out_size)
{
    (void)in_sizes; (void)n_in; (void)out_size;
    const float* input = (const float*)d_in[0];
    const float* h0    = (const float*)d_in[1];
    const float* c0    = (const float*)d_in[2];
    const float* W_ih  = (const float*)d_in[3];
    const float* W_hh  = (const float*)d_in[4];
    const float* b_ih  = (const float*)d_in[5];
    const float* b_hh  = (const float*)d_in[6];
    float* out = (float*)d_out;

    cudaFuncSetAttribute(lstm_recurrent,
                         cudaFuncAttributeMaxDynamicSharedMemorySize, SM_TOT);
    cudaFuncSetAttribute(xproj_mma,
                         cudaFuncAttributeMaxDynamicSharedMemorySize, SMEM_A_TOT);

    init_state<<<128, 256>>>(h0);
    convert_split<<<1024, 256>>>(input, W_ih);

    dim3 ggrid(G4 / 128, (TT * BB) / 128);   // (16, 256); m fast -> B-tile L2 reuse
    xproj_mma<<<ggrid, 256, SMEM_A_TOT>>>(b_ih, b_hh);

    lstm_recurrent<<<NCTA, 256, SM_TOT>>>(W_hh, c0, out);
}

// round 11
// speedup vs baseline: 1.9529x; 1.9529x over previous
#include <cuda_runtime.h>
#include <cuda_bf16.h>
#include <cuda_fp16.h>
#include <cstdint>

// Problem dims
#define TT   512
#define BB   64
#define II   512
#define HH   512
#define G4   2048          // 4*H gate rows
#define NCTA 128           // persistent CTAs for recurrence

// Phase A GEMM tiling (mma.sync bf16, base-target PTX only)
#define KCH     32
#define NCHK    (II / KCH)
#define SROW    40                  // padded smem row (elems)
#define TILEB   (128 * SROW * 2)
#define STAGEB  (4 * TILEB)
#define SMEM_A_TOT (2 * STAGEB)

// Phase B smem layout (bytes)
#define HS_PITCH 144                      // 128B h row + 16B pad (bank-shift 4)
#define W_PITCH  1040                     // 1024B W row + 16B pad
#define SM_HS2   0                        // h fp16 padded: 512*144 = 73728
#define SM_WS2   73728                    // W fp16 hi|lo: 2*16*1040 = 33280
#define SM_GSH2  (73728 + 33280)          // gates fp32 16x64 = 4096
#define SM_TOT2  (SM_GSH2 + 4096)         // 111104

typedef unsigned long long u64;

// ---------------------------------------------------------------------------
// Global scratch
// ---------------------------------------------------------------------------
__device__ __align__(256) float g_xp[(size_t)TT * G4 * BB];   // x_proj [t][g][b]
__device__ __align__(256) __half g_hh[2][HH * BB];            // h fp16, [k][b]
__device__ __nv_bfloat16 g_in_hi[(size_t)TT * BB * II];
__device__ __nv_bfloat16 g_in_lo[(size_t)TT * BB * II];
__device__ __nv_bfloat16 g_w_hi[(size_t)G4 * II];
__device__ __nv_bfloat16 g_w_lo[(size_t)G4 * II];
__device__ unsigned int          g_bar_cnt;
__device__ volatile unsigned int g_bar_gen;

// ---------------------------------------------------------------------------
// PTX helpers (base-target features only)
// ---------------------------------------------------------------------------
__device__ __forceinline__ uint32_t smem_u32(const void* p) {
    uint32_t a;
    asm("{ .reg .u64 t; cvta.to.shared.u64 t, %1; cvt.u32.u64 %0, t; }"
        : "=r"(a) : "l"(p));
    return a;
}
__device__ __forceinline__ void cpasync16(uint32_t dst, const void* src) {
    asm volatile("cp.async.cg.shared.global [%0], [%1], 16;"
                 :: "r"(dst), "l"(src) : "memory");
}
__device__ __forceinline__ void cp_commit() {
    asm volatile("cp.async.commit_group;" ::: "memory");
}
template <int N>
__device__ __forceinline__ void cp_wait() {
    asm volatile("cp.async.wait_group %0;" :: "n"(N) : "memory");
}
__device__ __forceinline__ void ldsm4(uint32_t* r, uint32_t addr) {
    asm volatile("ldmatrix.sync.aligned.m8n8.x4.shared.b16 {%0,%1,%2,%3}, [%4];"
                 : "=r"(r[0]), "=r"(r[1]), "=r"(r[2]), "=r"(r[3]) : "r"(addr));
}
__device__ __forceinline__ void ldsm4t(uint32_t* r, uint32_t addr) {
    asm volatile("ldmatrix.sync.aligned.m8n8.x4.trans.shared.b16 {%0,%1,%2,%3}, [%4];"
                 : "=r"(r[0]), "=r"(r[1]), "=r"(r[2]), "=r"(r[3]) : "r"(addr));
}
__device__ __forceinline__ void mma16816(float* d, const uint32_t* a, const uint32_t* b) {
    asm volatile(
        "mma.sync.aligned.m16n8k16.row.col.f32.bf16.bf16.f32 "
        "{%0,%1,%2,%3}, {%4,%5,%6,%7}, {%8,%9}, {%0,%1,%2,%3};"
        : "+f"(d[0]), "+f"(d[1]), "+f"(d[2]), "+f"(d[3])
        : "r"(a[0]), "r"(a[1]), "r"(a[2]), "r"(a[3]), "r"(b[0]), "r"(b[1]));
}
__device__ __forceinline__ void mma16816f(float* d, const uint32_t* a, const uint32_t* b) {
    asm volatile(
        "mma.sync.aligned.m16n8k16.row.col.f32.f16.f16.f32 "
        "{%0,%1,%2,%3}, {%4,%5,%6,%7}, {%8,%9}, {%0,%1,%2,%3};"
        : "+f"(d[0]), "+f"(d[1]), "+f"(d[2]), "+f"(d[3])
        : "r"(a[0]), "r"(a[1]), "r"(a[2]), "r"(a[3]), "r"(b[0]), "r"(b[1]));
}

__device__ __forceinline__ float sigf(float x) { return 1.0f / (1.0f + __expf(-x)); }
__device__ __forceinline__ float tanh_fast(float x) {
    return 1.0f - 2.0f / (1.0f + __expf(2.0f * x));
}

// release/acquire software grid barrier (all NCTA CTAs resident)
__device__ __forceinline__ void grid_barrier() {
    __syncthreads();
    if (threadIdx.x == 0) {
        __threadfence();
        unsigned old = g_bar_gen;
        if (atomicAdd(&g_bar_cnt, 1u) == NCTA - 1u) {
            g_bar_cnt = 0;
            __threadfence();
            g_bar_gen = old + 1u;
        } else {
            while (g_bar_gen == old) { }
        }
        __threadfence();
    }
    __syncthreads();
}

// ---------------------------------------------------------------------------
// Init: barrier reset + h0 transpose -> fp16 [k][b]
// ---------------------------------------------------------------------------
__global__ void init_state(const float* __restrict__ h0) {
    int i = blockIdx.x * blockDim.x + threadIdx.x;
    if (i == 0) { g_bar_cnt = 0; g_bar_gen = 0; }
    if (i < HH * BB) {
        int j = i >> 6, b = i & 63;
        g_hh[0][i] = __float2half_rn(h0[b * HH + j]);
    }
}

// ---------------------------------------------------------------------------
// Split fp32 -> bf16 hi/lo for input and W_ih (Phase A operands)
// ---------------------------------------------------------------------------
__global__ void convert_split(const float* __restrict__ input,
                              const float* __restrict__ W_ih) {
    const size_t n_in = (size_t)TT * BB * II;
    const size_t n_w  = (size_t)G4 * II;
    size_t stride = (size_t)gridDim.x * blockDim.x;
    for (size_t i = blockIdx.x * (size_t)blockDim.x + threadIdx.x; i < n_in; i += stride) {
        float x = input[i];
        __nv_bfloat16 h = __float2bfloat16(x);
        g_in_hi[i] = h;
        g_in_lo[i] = __float2bfloat16(x - __bfloat162float(h));
    }
    for (size_t i = blockIdx.x * (size_t)blockDim.x + threadIdx.x; i < n_w; i += stride) {
        float x = W_ih[i];
        __nv_bfloat16 h = __float2bfloat16(x);
        g_w_hi[i] = h;
        g_w_lo[i] = __float2bfloat16(x - __bfloat162float(h));
    }
}

// ---------------------------------------------------------------------------
// Phase A: x_proj via mma.sync bf16 split GEMM (3 passes) — unchanged (R6).
// ---------------------------------------------------------------------------
__device__ __forceinline__ void load_chunk_a(int c, int stage, int mbase, int nbase,
                                             uint32_t sbase) {
    const int tid = threadIdx.x;
    const uint32_t st = sbase + (uint32_t)stage * STAGEB;
    #pragma unroll
    for (int it = 0; it < 8; ++it) {
        int i = tid + it * 256;
        int which = i >> 10;
        int rem   = i & 1023;
        int hl    = (rem >> 9) & 1;
        int r     = (rem >> 2) & 127;
        int cc    = rem & 3;
        const __nv_bfloat16* gsrc =
            which ? (hl ? g_in_lo : g_in_hi) : (hl ? g_w_lo : g_w_hi);
        int grow = which ? (nbase + r) : (mbase + r);
        const void* src = gsrc + (size_t)grow * II + c * KCH + cc * 8;
        uint32_t dst = st + (uint32_t)which * (2 * TILEB) + (uint32_t)hl * TILEB
                     + (uint32_t)(r * (SROW * 2) + cc * 16);
        cpasync16(dst, src);
    }
    cp_commit();
}

__global__ void __launch_bounds__(256, 2)
xproj_mma(const float* __restrict__ b_ih, const float* __restrict__ b_hh) {
    extern __shared__ char dsm[];
    const uint32_t sbase = smem_u32(dsm);

    const int tid  = threadIdx.x;
    const int wid  = tid >> 5;
    const int lane = tid & 31;
    const int mbase = blockIdx.x * 128;
    const int nbase = blockIdx.y * 128;
    const int wm = (wid >> 2) * 64;
    const int wn = (wid & 3) * 32;

    uint32_t aoff[4], boff[2];
    {
        int l15 = lane & 15, lhi = lane >> 4;
        #pragma unroll
        for (int f = 0; f < 4; ++f)
            aoff[f] = (uint32_t)(((wm + f * 16 + l15) * SROW + lhi * 8) * 2);
        int sub = lane & 7, grp = lane >> 3;
        #pragma unroll
        for (int p = 0; p < 2; ++p)
            boff[p] = (uint32_t)(((wn + p * 16 + (grp >> 1) * 8 + sub) * SROW
                                  + (grp & 1) * 8) * 2);
    }

    float acc[4][4][4];
    #pragma unroll
    for (int f = 0; f < 4; ++f)
        #pragma unroll
        for (int n = 0; n < 4; ++n)
            #pragma unroll
            for (int e = 0; e < 4; ++e) acc[f][n][e] = 0.0f;

    load_chunk_a(0, 0, mbase, nbase, sbase);
    load_chunk_a(1, 1, mbase, nbase, sbase);

    for (int c = 0; c < NCHK; ++c) {
        if (c < NCHK - 1) cp_wait<1>();
        else              cp_wait<0>();
        __syncthreads();

        const uint32_t st = sbase + (uint32_t)(c & 1) * STAGEB;
        const uint32_t Ah = st, Al = st + TILEB, Bh = st + 2 * TILEB, Bl = st + 3 * TILEB;

        #pragma unroll
        for (int step = 0; step < 2; ++step) {
            const uint32_t ko = (uint32_t)step * 32;
            uint32_t ah[16], bh[8], bl[8];
            #pragma unroll
            for (int f = 0; f < 4; ++f) ldsm4(&ah[f * 4], Ah + aoff[f] + ko);
            #pragma unroll
            for (int p = 0; p < 2; ++p) {
                ldsm4(&bh[p * 4], Bh + boff[p] + ko);
                ldsm4(&bl[p * 4], Bl + boff[p] + ko);
            }
            #pragma unroll
            for (int f = 0; f < 4; ++f)
                #pragma unroll
                for (int n = 0; n < 4; ++n) {
                    mma16816(acc[f][n], &ah[f * 4], &bh[n * 2]);
                    mma16816(acc[f][n], &ah[f * 4], &bl[n * 2]);
                }
            uint32_t al[16];
            #pragma unroll
            for (int f = 0; f < 4; ++f) ldsm4(&al[f * 4], Al + aoff[f] + ko);
            #pragma unroll
            for (int f = 0; f < 4; ++f)
                #pragma unroll
                for (int n = 0; n < 4; ++n)
                    mma16816(acc[f][n], &al[f * 4], &bh[n * 2]);
        }
        __syncthreads();
        if (c + 2 < NCHK) load_chunk_a(c + 2, (c & 1), mbase, nbase, sbase);
    }

    const int rrow = lane >> 2;
    const int ncol = (lane & 3) * 2;
    #pragma unroll
    for (int f = 0; f < 4; ++f) {
        const int g0 = mbase + wm + f * 16 + rrow;
        const float bias0 = b_ih[g0] + b_hh[g0];
        const float bias1 = b_ih[g0 + 8] + b_hh[g0 + 8];
        #pragma unroll
        for (int n = 0; n < 4; ++n) {
            const int tb = nbase + wn + n * 8 + ncol;
            const int t  = tb >> 6;
            const int b  = tb & 63;
            float* base = g_xp + (size_t)t * (G4 * BB) + b;
            float2 v0 = make_float2(acc[f][n][0] + bias0, acc[f][n][1] + bias0);
            float2 v1 = make_float2(acc[f][n][2] + bias1, acc[f][n][3] + bias1);
            *(float2*)(base + (size_t)g0 * 64)       = v0;
            *(float2*)(base + (size_t)(g0 + 8) * 64) = v1;
        }
    }
}

// ---------------------------------------------------------------------------
// Phase B v3: persistent reverse recurrence on tensor cores (mma.sync f16).
// CTA owns 16 gate rows (local row r = q*4+jj <-> global q*512+jbase+jj).
// D[16x64] = W[16x512] @ h[512x64]: warps 0-3, each n=16 (2 m16n8 frags).
// A = W fp16 hi/lo in padded smem (static). B = h fp16 [k][b] copied per step
// into 144B-pitch smem (conflict-free ldmatrix.trans). 2 MMA passes (Whi,Wlo).
// ---------------------------------------------------------------------------
__global__ void __launch_bounds__(256, 1)
lstm_recurrent(const float* __restrict__ W_hh,
               const float* __restrict__ c0,
               float* __restrict__ out)
{
    extern __shared__ char smem[];
    float* gsh = (float*)(smem + SM_GSH2);
    const uint32_t hs_b = smem_u32(smem + SM_HS2);
    const uint32_t ws_b = smem_u32(smem + SM_WS2);

    const int tid   = threadIdx.x;
    const int wid   = tid >> 5;
    const int lane  = tid & 31;
    const int cta   = blockIdx.x;
    const int jbase = cta * 4;

    // W_hh slice -> fp16 hi/lo in padded smem (once)
    for (int idx = tid; idx < 16 * 512; idx += 256) {
        int r = idx >> 9, k = idx & 511;
        int grow = (r >> 2) * 512 + jbase + (r & 3);
        float w = W_hh[(size_t)grow * HH + k];
        __half whi = __float2half_rn(w);
        __half wlo = __float2half_rn(w - __half2float(whi));
        *(__half*)(smem + SM_WS2 + r * W_PITCH + k * 2)          = whi;
        *(__half*)(smem + SM_WS2 + 16640 + r * W_PITCH + k * 2)  = wlo;
    }

    // cell-update mapping + c state
    const int b_u = tid & 63, jj_u = tid >> 6;
    float c_reg = c0[b_u * HH + jbase + jj_u];
    __syncthreads();

    // mma-warp constants (warps 0-3)
    const uint32_t aH = ws_b + (uint32_t)((lane & 15) * W_PITCH + (lane >> 4) * 16);
    const uint32_t aL = aH + 16640u;
    const uint32_t bB = hs_b
        + (uint32_t)((((lane >> 3) & 1) * 8 + (lane & 7)) * HS_PITCH)
        + (uint32_t)(((lane >> 4) * 8 + wid * 16) * 2);
    const int rloc = lane >> 2;                       // local rows rloc, rloc+8
    const int bcol = wid * 16 + 2 * (lane & 3);       // batch col base
    const int gA = (rloc >> 2) * 512 + jbase + (rloc & 3);
    const int gB = ((rloc + 8) >> 2) * 512 + jbase + ((rloc + 8) & 3);

    for (int s = 0; s < TT; ++s) {
        const int t   = TT - 1 - s;
        const int cur = s & 1;

        // issue 4 chunk copies of h (128 k-rows each), all threads
        {
            const char* hsrc = (const char*)g_hh[cur];
            #pragma unroll
            for (int ch = 0; ch < 4; ++ch) {
                #pragma unroll
                for (int i = 0; i < 4; ++i) {
                    int op  = tid + i * 256;               // 0..1023
                    int row = ch * 128 + (op >> 3);
                    int col = op & 7;
                    cpasync16(hs_b + (uint32_t)(row * HS_PITCH + col * 16),
                              hsrc + row * 128 + col * 16);
                }
                cp_commit();
            }
        }

        // seed D fragments from x_proj
        float d0[4], d1[4];
        if (wid < 4) {
            const float* xp = g_xp + (size_t)t * (G4 * BB);
            float2 v;
            v = *(const float2*)(xp + (size_t)gA * 64 + bcol);     d0[0] = v.x; d0[1] = v.y;
            v = *(const float2*)(xp + (size_t)gB * 64 + bcol);     d0[2] = v.x; d0[3] = v.y;
            v = *(const float2*)(xp + (size_t)gA * 64 + bcol + 8); d1[0] = v.x; d1[1] = v.y;
            v = *(const float2*)(xp + (size_t)gB * 64 + bcol + 8); d1[2] = v.x; d1[3] = v.y;
        }

        // 4 chunks: wait copy, sync, 8 k-steps of MMA each
        #pragma unroll
        for (int ch = 0; ch < 4; ++ch) {
            if      (ch == 0) cp_wait<3>();
            else if (ch == 1) cp_wait<2>();
            else if (ch == 2) cp_wait<1>();
            else              cp_wait<0>();
            __syncthreads();

            if (wid < 4) {
                #pragma unroll
                for (int kk = 0; kk < 8; ++kk) {
                    const int ks = ch * 8 + kk;
                    uint32_t ah[4], al[4], bb[4];
                    ldsm4 (ah, aH + (uint32_t)(ks * 32));
                    ldsm4 (al, aL + (uint32_t)(ks * 32));
                    ldsm4t(bb, bB + (uint32_t)(ks * 16 * HS_PITCH));
                    mma16816f(d0, ah, &bb[0]);
                    mma16816f(d0, al, &bb[0]);
                    mma16816f(d1, ah, &bb[2]);
                    mma16816f(d1, al, &bb[2]);
                }
            }
        }

        // gates -> shared
        if (wid < 4) {
            *(float2*)&gsh[ rloc      * 64 + bcol]     = make_float2(d0[0], d0[1]);
            *(float2*)&gsh[(rloc + 8) * 64 + bcol]     = make_float2(d0[2], d0[3]);
            *(float2*)&gsh[ rloc      * 64 + bcol + 8] = make_float2(d1[0], d1[1]);
            *(float2*)&gsh[(rloc + 8) * 64 + bcol + 8] = make_float2(d1[2], d1[3]);
        }
        __syncthreads();

        // elementwise LSTM cell update: thread owns (b_u, j = jbase+jj_u)
        float gi = gsh[( 0 + jj_u) * 64 + b_u];
        float gf = gsh[( 4 + jj_u) * 64 + b_u];
        float gg = gsh[( 8 + jj_u) * 64 + b_u];
        float go = gsh[(12 + jj_u) * 64 + b_u];

        float ig = sigf(gi), fg = sigf(gf), og = sigf(go);
        c_reg = fg * c_reg + ig * tanh_fast(gg);
        float hn = og * tanh_fast(c_reg);

        const int jg = jbase + jj_u;
        g_hh[cur ^ 1][jg * 64 + b_u] = __float2half_rn(hn);
        out[(size_t)t * (BB * HH) + (size_t)b_u * HH + jg] = hn;
        if (s == TT - 1) {
            out[(size_t)TT * (BB * HH) + (size_t)b_u * HH + jg]           = hn;
            out[(size_t)TT * (BB * HH) + BB * HH + (size_t)b_u * HH + jg] = c_reg;
        }

        grid_barrier();   // release g_hh writes to all CTAs; fences smem reuse
    }
}

// ---------------------------------------------------------------------------
// Launch
// ---------------------------------------------------------------------------
extern "C" void kernel_launch(void* const* d_in, const int* in_sizes, int n_in,
                              void* d_out, int out_size)
{
    (void)in_sizes; (void)n_in; (void)out_size;
    const float* input = (const float*)d_in[0];
    const float* h0    = (const float*)d_in[1];
    const float* c0    = (const float*)d_in[2];
    const float* W_ih  = (const float*)d_in[3];
    const float* W_hh  = (const float*)d_in[4];
    const float* b_ih  = (const float*)d_in[5];
    const float* b_hh  = (const float*)d_in[6];
    float* out = (float*)d_out;

    cudaFuncSetAttribute(lstm_recurrent,
                         cudaFuncAttributeMaxDynamicSharedMemorySize, SM_TOT2);
    cudaFuncSetAttribute(xproj_mma,
                         cudaFuncAttributeMaxDynamicSharedMemorySize, SMEM_A_TOT);

    init_state<<<128, 256>>>(h0);
    convert_split<<<1024, 256>>>(input, W_ih);

    dim3 ggrid(G4 / 128, (TT * BB) / 128);   // (16, 256)
    xproj_mma<<<ggrid, 256, SMEM_A_TOT>>>(b_ih, b_hh);

    lstm_recurrent<<<NCTA, 256, SM_TOT2>>>(W_hh, c0, out);
}

// round 16
// speedup vs baseline: 2.2684x; 1.1615x over previous
#include <cuda_runtime.h>
#include <cuda_bf16.h>
#include <cuda_fp16.h>
#include <cstdint>

// Problem dims
#define TT   512
#define BB   64
#define II   512
#define HH   512
#define G4   2048          // 4*H gate rows
#define NCTA 128           // persistent CTAs for recurrence

// Phase A GEMM tiling (mma.sync bf16, base-target PTX only)
#define KCH     32
#define NCHK    (II / KCH)
#define SROW    40                  // padded smem row (elems)
#define TILEB   (128 * SROW * 2)
#define STAGEB  (4 * TILEB)
#define SMEM_A_TOT (2 * STAGEB)

// Phase B smem layout (bytes)
#define W_PITCH  1040                     // 1024B W row + 16B pad
#define SM_HS2   0                        // h fp16 swizzled: 512*128 = 65536
#define SM_WS2   65536                    // W fp16 hi|lo: 2*16*1040 = 33280
#define SM_GSH2  (65536 + 33280)          // gates fp32 16x64 = 4096
#define SM_MBAR2 (SM_GSH2 + 4096)         // 4 mbarriers
#define SM_TOT2  (SM_MBAR2 + 64)

typedef unsigned long long u64;

// ---------------------------------------------------------------------------
// Global scratch
// ---------------------------------------------------------------------------
__device__ __align__(256) float g_xp[(size_t)TT * G4 * BB];   // x_proj [t][g][b]
// h fp16, [k][b], 128B rows, 16B-chunk XOR swizzle: chunk c at c ^ (k&7)
__device__ __align__(256) __half g_hh[2][HH * BB];
__device__ __nv_bfloat16 g_in_hi[(size_t)TT * BB * II];
__device__ __nv_bfloat16 g_in_lo[(size_t)TT * BB * II];
__device__ __nv_bfloat16 g_w_hi[(size_t)G4 * II];
__device__ __nv_bfloat16 g_w_lo[(size_t)G4 * II];
__device__ unsigned int          g_bar_cnt;
__device__ volatile unsigned int g_bar_gen;

// swizzled byte offset of h element (k, b) within one g_hh buffer
__device__ __forceinline__ uint32_t h_swz(int k, int b) {
    return (uint32_t)(k * 128 + (((b >> 3) ^ (k & 7)) * 16) + (b & 7) * 2);
}

// ---------------------------------------------------------------------------
// PTX helpers (base-target features only)
// ---------------------------------------------------------------------------
__device__ __forceinline__ uint32_t smem_u32(const void* p) {
    uint32_t a;
    asm("{ .reg .u64 t; cvta.to.shared.u64 t, %1; cvt.u32.u64 %0, t; }"
        : "=r"(a) : "l"(p));
    return a;
}
__device__ __forceinline__ void mbar_init(uint32_t addr, uint32_t count) {
    asm volatile("mbarrier.init.shared.b64 [%0], %1;" :: "r"(addr), "r"(count) : "memory");
}
__device__ __forceinline__ void mbar_expect_tx(uint32_t addr, uint32_t bytes) {
    asm volatile("mbarrier.arrive.expect_tx.shared.b64 _, [%0], %1;"
                 :: "r"(addr), "r"(bytes) : "memory");
}
__device__ __forceinline__ void mbar_wait(uint32_t addr, uint32_t parity) {
    asm volatile(
        "{\n\t"
        ".reg .pred P1;\n\t"
        "LAB_WAIT%=:\n\t"
        "mbarrier.try_wait.parity.acquire.cta.shared::cta.b64 P1, [%0], %1, 0x989680;\n\t"
        "@P1 bra LAB_DONE%=;\n\t"
        "bra LAB_WAIT%=;\n\t"
        "LAB_DONE%=:\n\t"
        "}"
        :: "r"(addr), "r"(parity) : "memory");
}
__device__ __forceinline__ void bulk_g2s(uint32_t dst, const void* src,
                                         uint32_t bytes, uint32_t mbar) {
    asm volatile(
        "cp.async.bulk.shared::cluster.global.mbarrier::complete_tx::bytes [%0], [%1], %2, [%3];"
        :: "r"(dst), "l"(src), "r"(bytes), "r"(mbar) : "memory");
}
__device__ __forceinline__ void fence_proxy_async_cta() {
    asm volatile("fence.proxy.async.shared::cta;" ::: "memory");
}
__device__ __forceinline__ void cpasync16(uint32_t dst, const void* src) {
    asm volatile("cp.async.cg.shared.global [%0], [%1], 16;"
                 :: "r"(dst), "l"(src) : "memory");
}
__device__ __forceinline__ void cp_commit() {
    asm volatile("cp.async.commit_group;" ::: "memory");
}
template <int N>
__device__ __forceinline__ void cp_wait() {
    asm volatile("cp.async.wait_group %0;" :: "n"(N) : "memory");
}
__device__ __forceinline__ void ldsm4(uint32_t* r, uint32_t addr) {
    asm volatile("ldmatrix.sync.aligned.m8n8.x4.shared.b16 {%0,%1,%2,%3}, [%4];"
                 : "=r"(r[0]), "=r"(r[1]), "=r"(r[2]), "=r"(r[3]) : "r"(addr));
}
__device__ __forceinline__ void ldsm4t(uint32_t* r, uint32_t addr) {
    asm volatile("ldmatrix.sync.aligned.m8n8.x4.trans.shared.b16 {%0,%1,%2,%3}, [%4];"
                 : "=r"(r[0]), "=r"(r[1]), "=r"(r[2]), "=r"(r[3]) : "r"(addr));
}
__device__ __forceinline__ void mma16816(float* d, const uint32_t* a, const uint32_t* b) {
    asm volatile(
        "mma.sync.aligned.m16n8k16.row.col.f32.bf16.bf16.f32 "
        "{%0,%1,%2,%3}, {%4,%5,%6,%7}, {%8,%9}, {%0,%1,%2,%3};"
        : "+f"(d[0]), "+f"(d[1]), "+f"(d[2]), "+f"(d[3])
        : "r"(a[0]), "r"(a[1]), "r"(a[2]), "r"(a[3]), "r"(b[0]), "r"(b[1]));
}
__device__ __forceinline__ void mma16816f(float* d, const uint32_t* a, const uint32_t* b) {
    asm volatile(
        "mma.sync.aligned.m16n8k16.row.col.f32.f16.f16.f32 "
        "{%0,%1,%2,%3}, {%4,%5,%6,%7}, {%8,%9}, {%0,%1,%2,%3};"
        : "+f"(d[0]), "+f"(d[1]), "+f"(d[2]), "+f"(d[3])
        : "r"(a[0]), "r"(a[1]), "r"(a[2]), "r"(a[3]), "r"(b[0]), "r"(b[1]));
}

__device__ __forceinline__ float sigf(float x) { return 1.0f / (1.0f + __expf(-x)); }
__device__ __forceinline__ float tanh_fast(float x) {
    return 1.0f - 2.0f / (1.0f + __expf(2.0f * x));
}

// release/acquire software grid barrier (all NCTA CTAs resident)
__device__ __forceinline__ void grid_barrier() {
    __syncthreads();
    if (threadIdx.x == 0) {
        __threadfence();
        unsigned old = g_bar_gen;
        if (atomicAdd(&g_bar_cnt, 1u) == NCTA - 1u) {
            g_bar_cnt = 0;
            __threadfence();
            g_bar_gen = old + 1u;
        } else {
            while (g_bar_gen == old) { }
        }
        __threadfence();
    }
    __syncthreads();
}

// ---------------------------------------------------------------------------
// Init: barrier reset + h0 transpose -> fp16 swizzled [k][b]
// ---------------------------------------------------------------------------
__global__ void init_state(const float* __restrict__ h0) {
    int i = blockIdx.x * blockDim.x + threadIdx.x;
    if (i == 0) { g_bar_cnt = 0; g_bar_gen = 0; }
    if (i < HH * BB) {
        int j = i >> 6, b = i & 63;
        *(__half*)((char*)g_hh[0] + h_swz(j, b)) = __float2half_rn(h0[b * HH + j]);
    }
}

// ---------------------------------------------------------------------------
// Split fp32 -> bf16 hi/lo for input and W_ih (Phase A operands)
// ---------------------------------------------------------------------------
__global__ void convert_split(const float* __restrict__ input,
                              const float* __restrict__ W_ih) {
    const size_t n_in = (size_t)TT * BB * II;
    const size_t n_w  = (size_t)G4 * II;
    size_t stride = (size_t)gridDim.x * blockDim.x;
    for (size_t i = blockIdx.x * (size_t)blockDim.x + threadIdx.x; i < n_in; i += stride) {
        float x = input[i];
        __nv_bfloat16 h = __float2bfloat16(x);
        g_in_hi[i] = h;
        g_in_lo[i] = __float2bfloat16(x - __bfloat162float(h));
    }
    for (size_t i = blockIdx.x * (size_t)blockDim.x + threadIdx.x; i < n_w; i += stride) {
        float x = W_ih[i];
        __nv_bfloat16 h = __float2bfloat16(x);
        g_w_hi[i] = h;
        g_w_lo[i] = __float2bfloat16(x - __bfloat162float(h));
    }
}

// ---------------------------------------------------------------------------
// Phase A: x_proj via mma.sync bf16 split GEMM (3 passes) — unchanged (R6).
// ---------------------------------------------------------------------------
__device__ __forceinline__ void load_chunk_a(int c, int stage, int mbase, int nbase,
                                             uint32_t sbase) {
    const int tid = threadIdx.x;
    const uint32_t st = sbase + (uint32_t)stage * STAGEB;
    #pragma unroll
    for (int it = 0; it < 8; ++it) {
        int i = tid + it * 256;
        int which = i >> 10;
        int rem   = i & 1023;
        int hl    = (rem >> 9) & 1;
        int r     = (rem >> 2) & 127;
        int cc    = rem & 3;
        const __nv_bfloat16* gsrc =
            which ? (hl ? g_in_lo : g_in_hi) : (hl ? g_w_lo : g_w_hi);
        int grow = which ? (nbase + r) : (mbase + r);
        const void* src = gsrc + (size_t)grow * II + c * KCH + cc * 8;
        uint32_t dst = st + (uint32_t)which * (2 * TILEB) + (uint32_t)hl * TILEB
                     + (uint32_t)(r * (SROW * 2) + cc * 16);
        cpasync16(dst, src);
    }
    cp_commit();
}

__global__ void __launch_bounds__(256, 2)
xproj_mma(const float* __restrict__ b_ih, const float* __restrict__ b_hh) {
    extern __shared__ char dsm[];
    const uint32_t sbase = smem_u32(dsm);

    const int tid  = threadIdx.x;
    const int wid  = tid >> 5;
    const int lane = tid & 31;
    const int mbase = blockIdx.x * 128;
    const int nbase = blockIdx.y * 128;
    const int wm = (wid >> 2) * 64;
    const int wn = (wid & 3) * 32;

    uint32_t aoff[4], boff[2];
    {
        int l15 = lane & 15, lhi = lane >> 4;
        #pragma unroll
        for (int f = 0; f < 4; ++f)
            aoff[f] = (uint32_t)(((wm + f * 16 + l15) * SROW + lhi * 8) * 2);
        int sub = lane & 7, grp = lane >> 3;
        #pragma unroll
        for (int p = 0; p < 2; ++p)
            boff[p] = (uint32_t)(((wn + p * 16 + (grp >> 1) * 8 + sub) * SROW
                                  + (grp & 1) * 8) * 2);
    }

    float acc[4][4][4];
    #pragma unroll
    for (int f = 0; f < 4; ++f)
        #pragma unroll
        for (int n = 0; n < 4; ++n)
            #pragma unroll
            for (int e = 0; e < 4; ++e) acc[f][n][e] = 0.0f;

    load_chunk_a(0, 0, mbase, nbase, sbase);
    load_chunk_a(1, 1, mbase, nbase, sbase);

    for (int c = 0; c < NCHK; ++c) {
        if (c < NCHK - 1) cp_wait<1>();
        else              cp_wait<0>();
        __syncthreads();

        const uint32_t st = sbase + (uint32_t)(c & 1) * STAGEB;
        const uint32_t Ah = st, Al = st + TILEB, Bh = st + 2 * TILEB, Bl = st + 3 * TILEB;

        #pragma unroll
        for (int step = 0; step < 2; ++step) {
            const uint32_t ko = (uint32_t)step * 32;
            uint32_t ah[16], bh[8], bl[8];
            #pragma unroll
            for (int f = 0; f < 4; ++f) ldsm4(&ah[f * 4], Ah + aoff[f] + ko);
            #pragma unroll
            for (int p = 0; p < 2; ++p) {
                ldsm4(&bh[p * 4], Bh + boff[p] + ko);
                ldsm4(&bl[p * 4], Bl + boff[p] + ko);
            }
            #pragma unroll
            for (int f = 0; f < 4; ++f)
                #pragma unroll
                for (int n = 0; n < 4; ++n) {
                    mma16816(acc[f][n], &ah[f * 4], &bh[n * 2]);
                    mma16816(acc[f][n], &ah[f * 4], &bl[n * 2]);
                }
            uint32_t al[16];
            #pragma unroll
            for (int f = 0; f < 4; ++f) ldsm4(&al[f * 4], Al + aoff[f] + ko);
            #pragma unroll
            for (int f = 0; f < 4; ++f)
                #pragma unroll
                for (int n = 0; n < 4; ++n)
                    mma16816(acc[f][n], &al[f * 4], &bh[n * 2]);
        }
        __syncthreads();
        if (c + 2 < NCHK) load_chunk_a(c + 2, (c & 1), mbase, nbase, sbase);
    }

    const int rrow = lane >> 2;
    const int ncol = (lane & 3) * 2;
    #pragma unroll
    for (int f = 0; f < 4; ++f) {
        const int g0 = mbase + wm + f * 16 + rrow;
        const float bias0 = b_ih[g0] + b_hh[g0];
        const float bias1 = b_ih[g0 + 8] + b_hh[g0 + 8];
        #pragma unroll
        for (int n = 0; n < 4; ++n) {
            const int tb = nbase + wn + n * 8 + ncol;
            const int t  = tb >> 6;
            const int b  = tb & 63;
            float* base = g_xp + (size_t)t * (G4 * BB) + b;
            float2 v0 = make_float2(acc[f][n][0] + bias0, acc[f][n][1] + bias0);
            float2 v1 = make_float2(acc[f][n][2] + bias1, acc[f][n][3] + bias1);
            *(float2*)(base + (size_t)g0 * 64)       = v0;
            *(float2*)(base + (size_t)(g0 + 8) * 64) = v1;
        }
    }
}

// ---------------------------------------------------------------------------
// Phase B v4: tensor-core recurrence + cp.async.bulk h staging.
// h lives in global in a 16B-chunk XOR-swizzled [k][b] fp16 layout so a LINEAR
// bulk copy produces conflict-free ldmatrix.trans rows in smem.
// Per step: tid0 issues 4x16KB bulk copies -> per-chunk mbar wait (mma warps
// only) -> 2-pass fp16 MMA -> cell update -> grid barrier.
// ---------------------------------------------------------------------------
__global__ void __launch_bounds__(256, 1)
lstm_recurrent(const float* __restrict__ W_hh,
               const float* __restrict__ c0,
               float* __restrict__ out)
{
    extern __shared__ char smem[];
    float* gsh = (float*)(smem + SM_GSH2);
    const uint32_t hs_b  = smem_u32(smem + SM_HS2);
    const uint32_t ws_b  = smem_u32(smem + SM_WS2);
    const uint32_t mbar0 = smem_u32(smem + SM_MBAR2);

    const int tid   = threadIdx.x;
    const int wid   = tid >> 5;
    const int lane  = tid & 31;
    const int cta   = blockIdx.x;
    const int jbase = cta * 4;

    // W_hh slice -> fp16 hi/lo in padded smem (once)
    for (int idx = tid; idx < 16 * 512; idx += 256) {
        int r = idx >> 9, k = idx & 511;
        int grow = (r >> 2) * 512 + jbase + (r & 3);
        float w = W_hh[(size_t)grow * HH + k];
        __half whi = __float2half_rn(w);
        __half wlo = __float2half_rn(w - __half2float(whi));
        *(__half*)(smem + SM_WS2 + r * W_PITCH + k * 2)          = whi;
        *(__half*)(smem + SM_WS2 + 16640 + r * W_PITCH + k * 2)  = wlo;
    }

    // cell-update mapping + c state
    const int b_u = tid & 63, jj_u = tid >> 6;
    float c_reg = c0[b_u * HH + jbase + jj_u];

    if (tid == 0) {
        #pragma unroll
        for (int i = 0; i < 4; ++i) mbar_init(mbar0 + 8 * i, 1);
    }
    fence_proxy_async_cta();
    __syncthreads();

    // mma-warp constants (warps 0-3)
    const uint32_t aH = ws_b + (uint32_t)((lane & 15) * W_PITCH + (lane >> 4) * 16);
    const uint32_t aL = aH + 16640u;
    // B fragment: lane row r16 (within 16-row chunk), logical 16B chunk bch0,
    // physical chunk bch0 ^ (k&7) = bch0 ^ (lane&7)
    const int r16  = (lane & 7) + 8 * ((lane >> 3) & 1);
    const int bch0 = wid * 2 + (lane >> 4);
    const uint32_t bB = hs_b + (uint32_t)(r16 * 128 + ((bch0 ^ (lane & 7)) * 16));
    const int rloc = lane >> 2;                       // local rows rloc, rloc+8
    const int bcol = wid * 16 + 2 * (lane & 3);       // batch col base
    const int gA = (rloc >> 2) * 512 + jbase + (rloc & 3);
    const int gB = ((rloc + 8) >> 2) * 512 + jbase + ((rloc + 8) & 3);

    for (int s = 0; s < TT; ++s) {
        const int t   = TT - 1 - s;
        const int cur = s & 1;
        const uint32_t phase = (uint32_t)(s & 1);

        // stage h: 4 pipelined 16KB bulk copies (single-thread issue)
        if (tid == 0) {
            fence_proxy_async_cta();
            const char* src = (const char*)g_hh[cur];
            #pragma unroll
            for (int ch = 0; ch < 4; ++ch) {
                mbar_expect_tx(mbar0 + 8 * ch, 16384u);
                bulk_g2s(hs_b + (uint32_t)ch * 16384u, src + ch * 16384,
                         16384u, mbar0 + 8 * ch);
            }
        }

        // seed D fragments from x_proj (LDG overlaps bulk copy latency)
        float d0[4], d1[4];
        if (wid < 4) {
            const float* xp = g_xp + (size_t)t * (G4 * BB);
            float2 v;
            v = *(const float2*)(xp + (size_t)gA * 64 + bcol);     d0[0] = v.x; d0[1] = v.y;
            v = *(const float2*)(xp + (size_t)gB * 64 + bcol);     d0[2] = v.x; d0[3] = v.y;
            v = *(const float2*)(xp + (size_t)gA * 64 + bcol + 8); d1[0] = v.x; d1[1] = v.y;
            v = *(const float2*)(xp + (size_t)gB * 64 + bcol + 8); d1[2] = v.x; d1[3] = v.y;

            // 4 chunks: mbar wait (no __syncthreads), 8 k-steps of MMA each
            #pragma unroll
            for (int ch = 0; ch < 4; ++ch) {
                mbar_wait(mbar0 + 8 * ch, phase);
                #pragma unroll
                for (int kk = 0; kk < 8; ++kk) {
                    const int ks = ch * 8 + kk;
                    uint32_t ah[4], al[4], bb[4];
                    ldsm4 (ah, aH + (uint32_t)(ks * 32));
                    ldsm4 (al, aL + (uint32_t)(ks * 32));
                    ldsm4t(bb, bB + (uint32_t)(ks * 2048));
                    mma16816f(d0, ah, &bb[0]);
                    mma16816f(d0, al, &bb[0]);
                    mma16816f(d1, ah, &bb[2]);
                    mma16816f(d1, al, &bb[2]);
                }
            }

            // gates -> shared
            *(float2*)&gsh[ rloc      * 64 + bcol]     = make_float2(d0[0], d0[1]);
            *(float2*)&gsh[(rloc + 8) * 64 + bcol]     = make_float2(d0[2], d0[3]);
            *(float2*)&gsh[ rloc      * 64 + bcol + 8] = make_float2(d1[0], d1[1]);
            *(float2*)&gsh[(rloc + 8) * 64 + bcol + 8] = make_float2(d1[2], d1[3]);
        }
        __syncthreads();

        // elementwise LSTM cell update: thread owns (b_u, j = jbase+jj_u)
        float gi = gsh[( 0 + jj_u) * 64 + b_u];
        float gf = gsh[( 4 + jj_u) * 64 + b_u];
        float gg = gsh[( 8 + jj_u) * 64 + b_u];
        float go = gsh[(12 + jj_u) * 64 + b_u];

        float ig = sigf(gi), fg = sigf(gf), og = sigf(go);
        c_reg = fg * c_reg + ig * tanh_fast(gg);
        float hn = og * tanh_fast(c_reg);

        const int jg = jbase + jj_u;
        *(__half*)((char*)g_hh[cur ^ 1] + h_swz(jg, b_u)) = __float2half_rn(hn);
        out[(size_t)t * (BB * HH) + (size_t)b_u * HH + jg] = hn;
        if (s == TT - 1) {
            out[(size_t)TT * (BB * HH) + (size_t)b_u * HH + jg]           = hn;
            out[(size_t)TT * (BB * HH) + BB * HH + (size_t)b_u * HH + jg] = c_reg;
        }

        grid_barrier();   // release g_hh writes to all CTAs; fences smem reuse
    }
}

// ---------------------------------------------------------------------------
// Launch
// ---------------------------------------------------------------------------
extern "C" void kernel_launch(void* const* d_in, const int* in_sizes, int n_in,
                              void* d_out, int out_size)
{
    (void)in_sizes; (void)n_in; (void)out_size;
    const float* input = (const float*)d_in[0];
    const float* h0    = (const float*)d_in[1];
    const float* c0    = (const float*)d_in[2];
    const float* W_ih  = (const float*)d_in[3];
    const float* W_hh  = (const float*)d_in[4];
    const float* b_ih  = (const float*)d_in[5];
    const float* b_hh  = (const float*)d_in[6];
    float* out = (float*)d_out;

    cudaFuncSetAttribute(lstm_recurrent,
                         cudaFuncAttributeMaxDynamicSharedMemorySize, SM_TOT2);
    cudaFuncSetAttribute(xproj_mma,
                         cudaFuncAttributeMaxDynamicSharedMemorySize, SMEM_A_TOT);

    init_state<<<128, 256>>>(h0);
    convert_split<<<1024, 256>>>(input, W_ih);

    dim3 ggrid(G4 / 128, (TT * BB) / 128);   // (16, 256)
    xproj_mma<<<ggrid, 256, SMEM_A_TOT>>>(b_ih, b_hh);

    lstm_recurrent<<<NCTA, 256, SM_TOT2>>>(W_hh, c0, out);
}

// round 17
// speedup vs baseline: 2.7580x; 1.2159x over previous
#include <cuda_runtime.h>
#include <cuda_bf16.h>
#include <cuda_fp16.h>
#include <cstdint>

// Problem dims
#define TT   512
#define BB   64
#define II   512
#define HH   512
#define G4   2048          // 4*H gate rows
#define NCTA 128           // persistent CTAs for recurrence

// Phase A GEMM tiling (mma.sync bf16, base-target PTX only)
#define KCH     32
#define NCHK    (II / KCH)
#define SROW    40                  // padded smem row (elems)
#define TILEB   (128 * SROW * 2)
#define STAGEB  (4 * TILEB)
#define SMEM_A_TOT (2 * STAGEB)

// Phase B smem layout (bytes)
#define W_PITCH  1040                     // 1024B W row + 16B pad
#define SM_HSB   0                        // h fp16 swizzled, DOUBLE buffer: 2*65536
#define SM_WS3   131072                   // W fp16 hi|lo: 2*16*1040 = 33280
#define SM_GSH3  (131072 + 33280)         // gates fp32 16x64 = 4096
#define SM_MBAR3 (SM_GSH3 + 4096)         // 8 mbarriers (2 buf x 4 chunk)
#define SM_TOT3  (SM_MBAR3 + 64)          // 168512

typedef unsigned long long u64;

// ---------------------------------------------------------------------------
// Global scratch
// ---------------------------------------------------------------------------
__device__ __align__(256) float g_xp[(size_t)TT * G4 * BB];   // x_proj [t][g][b]
// h fp16, [k][b], 128B rows, 16B-chunk XOR swizzle: chunk c at c ^ (k&7)
__device__ __align__(256) __half g_hh[2][HH * BB];
__device__ __nv_bfloat16 g_in_hi[(size_t)TT * BB * II];
__device__ __nv_bfloat16 g_in_lo[(size_t)TT * BB * II];
__device__ __nv_bfloat16 g_w_hi[(size_t)G4 * II];
__device__ __nv_bfloat16 g_w_lo[(size_t)G4 * II];
__device__ unsigned int g_cnt[4];          // per-chunk producer arrival counters

// swizzled byte offset of h element (k, b) within one g_hh buffer
__device__ __forceinline__ uint32_t h_swz(int k, int b) {
    return (uint32_t)(k * 128 + (((b >> 3) ^ (k & 7)) * 16) + (b & 7) * 2);
}

// ---------------------------------------------------------------------------
// PTX helpers (base-target features only)
// ---------------------------------------------------------------------------
__device__ __forceinline__ uint32_t smem_u32(const void* p) {
    uint32_t a;
    asm("{ .reg .u64 t; cvta.to.shared.u64 t, %1; cvt.u32.u64 %0, t; }"
        : "=r"(a) : "l"(p));
    return a;
}
__device__ __forceinline__ void mbar_init(uint32_t addr, uint32_t count) {
    asm volatile("mbarrier.init.shared.b64 [%0], %1;" :: "r"(addr), "r"(count) : "memory");
}
__device__ __forceinline__ void mbar_expect_tx(uint32_t addr, uint32_t bytes) {
    asm volatile("mbarrier.arrive.expect_tx.shared.b64 _, [%0], %1;"
                 :: "r"(addr), "r"(bytes) : "memory");
}
__device__ __forceinline__ void mbar_wait(uint32_t addr, uint32_t parity) {
    asm volatile(
        "{\n\t"
        ".reg .pred P1;\n\t"
        "LAB_WAIT%=:\n\t"
        "mbarrier.try_wait.parity.acquire.cta.shared::cta.b64 P1, [%0], %1, 0x989680;\n\t"
        "@P1 bra LAB_DONE%=;\n\t"
        "bra LAB_WAIT%=;\n\t"
        "LAB_DONE%=:\n\t"
        "}"
        :: "r"(addr), "r"(parity) : "memory");
}
__device__ __forceinline__ void bulk_g2s(uint32_t dst, const void* src,
                                         uint32_t bytes, uint32_t mbar) {
    asm volatile(
        "cp.async.bulk.shared::cluster.global.mbarrier::complete_tx::bytes [%0], [%1], %2, [%3];"
        :: "r"(dst), "l"(src), "r"(bytes), "r"(mbar) : "memory");
}
__device__ __forceinline__ void fence_proxy_async_cta() {
    asm volatile("fence.proxy.async.shared::cta;" ::: "memory");
}
__device__ __forceinline__ unsigned ld_acq(const unsigned* p) {
    unsigned v;
    asm volatile("ld.acquire.gpu.u32 %0, [%1];" : "=r"(v) : "l"(p) : "memory");
    return v;
}
__device__ __forceinline__ void red_release(unsigned* p) {
    asm volatile("red.release.gpu.global.add.u32 [%0], %1;" :: "l"(p), "r"(1u) : "memory");
}
__device__ __forceinline__ void cpasync16(uint32_t dst, const void* src) {
    asm volatile("cp.async.cg.shared.global [%0], [%1], 16;"
                 :: "r"(dst), "l"(src) : "memory");
}
__device__ __forceinline__ void cp_commit() {
    asm volatile("cp.async.commit_group;" ::: "memory");
}
template <int N>
__device__ __forceinline__ void cp_wait() {
    asm volatile("cp.async.wait_group %0;" :: "n"(N) : "memory");
}
__device__ __forceinline__ void ldsm4(uint32_t* r, uint32_t addr) {
    asm volatile("ldmatrix.sync.aligned.m8n8.x4.shared.b16 {%0,%1,%2,%3}, [%4];"
                 : "=r"(r[0]), "=r"(r[1]), "=r"(r[2]), "=r"(r[3]) : "r"(addr));
}
__device__ __forceinline__ void ldsm4t(uint32_t* r, uint32_t addr) {
    asm volatile("ldmatrix.sync.aligned.m8n8.x4.trans.shared.b16 {%0,%1,%2,%3}, [%4];"
                 : "=r"(r[0]), "=r"(r[1]), "=r"(r[2]), "=r"(r[3]) : "r"(addr));
}
__device__ __forceinline__ void mma16816(float* d, const uint32_t* a, const uint32_t* b) {
    asm volatile(
        "mma.sync.aligned.m16n8k16.row.col.f32.bf16.bf16.f32 "
        "{%0,%1,%2,%3}, {%4,%5,%6,%7}, {%8,%9}, {%0,%1,%2,%3};"
        : "+f"(d[0]), "+f"(d[1]), "+f"(d[2]), "+f"(d[3])
        : "r"(a[0]), "r"(a[1]), "r"(a[2]), "r"(a[3]), "r"(b[0]), "r"(b[1]));
}
__device__ __forceinline__ void mma16816f(float* d, const uint32_t* a, const uint32_t* b) {
    asm volatile(
        "mma.sync.aligned.m16n8k16.row.col.f32.f16.f16.f32 "
        "{%0,%1,%2,%3}, {%4,%5,%6,%7}, {%8,%9}, {%0,%1,%2,%3};"
        : "+f"(d[0]), "+f"(d[1]), "+f"(d[2]), "+f"(d[3])
        : "r"(a[0]), "r"(a[1]), "r"(a[2]), "r"(a[3]), "r"(b[0]), "r"(b[1]));
}

__device__ __forceinline__ float sigf(float x) { return 1.0f / (1.0f + __expf(-x)); }
__device__ __forceinline__ float tanh_fast(float x) {
    return 1.0f - 2.0f / (1.0f + __expf(2.0f * x));
}

// ---------------------------------------------------------------------------
// Init: counter reset + h0 transpose -> fp16 swizzled [k][b]
// ---------------------------------------------------------------------------
__global__ void init_state(const float* __restrict__ h0) {
    int i = blockIdx.x * blockDim.x + threadIdx.x;
    if (i < 4) g_cnt[i] = 0;
    if (i < HH * BB) {
        int j = i >> 6, b = i & 63;
        *(__half*)((char*)g_hh[0] + h_swz(j, b)) = __float2half_rn(h0[b * HH + j]);
    }
}

// ---------------------------------------------------------------------------
// Split fp32 -> bf16 hi/lo for input and W_ih (Phase A operands)
// ---------------------------------------------------------------------------
__global__ void convert_split(const float* __restrict__ input,
                              const float* __restrict__ W_ih) {
    const size_t n_in = (size_t)TT * BB * II;
    const size_t n_w  = (size_t)G4 * II;
    size_t stride = (size_t)gridDim.x * blockDim.x;
    for (size_t i = blockIdx.x * (size_t)blockDim.x + threadIdx.x; i < n_in; i += stride) {
        float x = input[i];
        __nv_bfloat16 h = __float2bfloat16(x);
        g_in_hi[i] = h;
        g_in_lo[i] = __float2bfloat16(x - __bfloat162float(h));
    }
    for (size_t i = blockIdx.x * (size_t)blockDim.x + threadIdx.x; i < n_w; i += stride) {
        float x = W_ih[i];
        __nv_bfloat16 h = __float2bfloat16(x);
        g_w_hi[i] = h;
        g_w_lo[i] = __float2bfloat16(x - __bfloat162float(h));
    }
}

// ---------------------------------------------------------------------------
// Phase A: x_proj via mma.sync bf16 split GEMM (3 passes) — unchanged (R6).
// ---------------------------------------------------------------------------
__device__ __forceinline__ void load_chunk_a(int c, int stage, int mbase, int nbase,
                                             uint32_t sbase) {
    const int tid = threadIdx.x;
    const uint32_t st = sbase + (uint32_t)stage * STAGEB;
    #pragma unroll
    for (int it = 0; it < 8; ++it) {
        int i = tid + it * 256;
        int which = i >> 10;
        int rem   = i & 1023;
        int hl    = (rem >> 9) & 1;
        int r     = (rem >> 2) & 127;
        int cc    = rem & 3;
        const __nv_bfloat16* gsrc =
            which ? (hl ? g_in_lo : g_in_hi) : (hl ? g_w_lo : g_w_hi);
        int grow = which ? (nbase + r) : (mbase + r);
        const void* src = gsrc + (size_t)grow * II + c * KCH + cc * 8;
        uint32_t dst = st + (uint32_t)which * (2 * TILEB) + (uint32_t)hl * TILEB
                     + (uint32_t)(r * (SROW * 2) + cc * 16);
        cpasync16(dst, src);
    }
    cp_commit();
}

__global__ void __launch_bounds__(256, 2)
xproj_mma(const float* __restrict__ b_ih, const float* __restrict__ b_hh) {
    extern __shared__ char dsm[];
    const uint32_t sbase = smem_u32(dsm);

    const int tid  = threadIdx.x;
    const int wid  = tid >> 5;
    const int lane = tid & 31;
    const int mbase = blockIdx.x * 128;
    const int nbase = blockIdx.y * 128;
    const int wm = (wid >> 2) * 64;
    const int wn = (wid & 3) * 32;

    uint32_t aoff[4], boff[2];
    {
        int l15 = lane & 15, lhi = lane >> 4;
        #pragma unroll
        for (int f = 0; f < 4; ++f)
            aoff[f] = (uint32_t)(((wm + f * 16 + l15) * SROW + lhi * 8) * 2);
        int sub = lane & 7, grp = lane >> 3;
        #pragma unroll
        for (int p = 0; p < 2; ++p)
            boff[p] = (uint32_t)(((wn + p * 16 + (grp >> 1) * 8 + sub) * SROW
                                  + (grp & 1) * 8) * 2);
    }

    float acc[4][4][4];
    #pragma unroll
    for (int f = 0; f < 4; ++f)
        #pragma unroll
        for (int n = 0; n < 4; ++n)
            #pragma unroll
            for (int e = 0; e < 4; ++e) acc[f][n][e] = 0.0f;

    load_chunk_a(0, 0, mbase, nbase, sbase);
    load_chunk_a(1, 1, mbase, nbase, sbase);

    for (int c = 0; c < NCHK; ++c) {
        if (c < NCHK - 1) cp_wait<1>();
        else              cp_wait<0>();
        __syncthreads();

        const uint32_t st = sbase + (uint32_t)(c & 1) * STAGEB;
        const uint32_t Ah = st, Al = st + TILEB, Bh = st + 2 * TILEB, Bl = st + 3 * TILEB;

        #pragma unroll
        for (int step = 0; step < 2; ++step) {
            const uint32_t ko = (uint32_t)step * 32;
            uint32_t ah[16], bh[8], bl[8];
            #pragma unroll
            for (int f = 0; f < 4; ++f) ldsm4(&ah[f * 4], Ah + aoff[f] + ko);
            #pragma unroll
            for (int p = 0; p < 2; ++p) {
                ldsm4(&bh[p * 4], Bh + boff[p] + ko);
                ldsm4(&bl[p * 4], Bl + boff[p] + ko);
            }
            #pragma unroll
            for (int f = 0; f < 4; ++f)
                #pragma unroll
                for (int n = 0; n < 4; ++n) {
                    mma16816(acc[f][n], &ah[f * 4], &bh[n * 2]);
                    mma16816(acc[f][n], &ah[f * 4], &bl[n * 2]);
                }
            uint32_t al[16];
            #pragma unroll
            for (int f = 0; f < 4; ++f) ldsm4(&al[f * 4], Al + aoff[f] + ko);
            #pragma unroll
            for (int f = 0; f < 4; ++f)
                #pragma unroll
                for (int n = 0; n < 4; ++n)
                    mma16816(acc[f][n], &al[f * 4], &bh[n * 2]);
        }
        __syncthreads();
        if (c + 2 < NCHK) load_chunk_a(c + 2, (c & 1), mbase, nbase, sbase);
    }

    const int rrow = lane >> 2;
    const int ncol = (lane & 3) * 2;
    #pragma unroll
    for (int f = 0; f < 4; ++f) {
        const int g0 = mbase + wm + f * 16 + rrow;
        const float bias0 = b_ih[g0] + b_hh[g0];
        const float bias1 = b_ih[g0 + 8] + b_hh[g0 + 8];
        #pragma unroll
        for (int n = 0; n < 4; ++n) {
            const int tb = nbase + wn + n * 8 + ncol;
            const int t  = tb >> 6;
            const int b  = tb & 63;
            float* base = g_xp + (size_t)t * (G4 * BB) + b;
            float2 v0 = make_float2(acc[f][n][0] + bias0, acc[f][n][1] + bias0);
            float2 v1 = make_float2(acc[f][n][2] + bias1, acc[f][n][3] + bias1);
            *(float2*)(base + (size_t)g0 * 64)       = v0;
            *(float2*)(base + (size_t)(g0 + 8) * 64) = v1;
        }
    }
}

// ---------------------------------------------------------------------------
// Phase B v5: tensor-core recurrence, chunk-granular dataflow sync.
// No grid barrier. h chunk ch (k-rows 128ch..128ch+127) is produced by CTAs
// 32ch..32ch+31; a monotonic counter per chunk gates the consumer-side bulk
// copy. Double-buffered smem h + double global h buffer. Warps 0-3 = MMA,
// warps 4-7 = cell update (2 elements/thread); tid 128 = issuer.
// ---------------------------------------------------------------------------
__global__ void __launch_bounds__(256, 1)
lstm_recurrent(const float* __restrict__ W_hh,
               const float* __restrict__ c0,
               float* __restrict__ out)
{
    extern __shared__ char smem[];
    float* gsh = (float*)(smem + SM_GSH3);
    const uint32_t hs_b  = smem_u32(smem + SM_HSB);
    const uint32_t ws_b  = smem_u32(smem + SM_WS3);
    const uint32_t mbar0 = smem_u32(smem + SM_MBAR3);

    const int tid   = threadIdx.x;
    const int wid   = tid >> 5;
    const int lane  = tid & 31;
    const int cta   = blockIdx.x;
    const int jbase = cta * 4;

    // W_hh slice -> fp16 hi/lo in padded smem (once)
    for (int idx = tid; idx < 16 * 512; idx += 256) {
        int r = idx >> 9, k = idx & 511;
        int grow = (r >> 2) * 512 + jbase + (r & 3);
        float w = W_hh[(size_t)grow * HH + k];
        __half whi = __float2half_rn(w);
        __half wlo = __float2half_rn(w - __half2float(whi));
        *(__half*)(smem + SM_WS3 + r * W_PITCH + k * 2)          = whi;
        *(__half*)(smem + SM_WS3 + 16640 + r * W_PITCH + k * 2)  = wlo;
    }

    if (tid == 0) {
        #pragma unroll
        for (int i = 0; i < 8; ++i) mbar_init(mbar0 + 8 * i, 1);
    }

    // cell-role state (warps 4-7): thread u handles (jj0=u>>6, b) and (jj0+2, b)
    const int u   = tid - 128;
    const int b_u = u & 63;
    const int jj0 = (u >> 6);          // 0 or 1
    float c_reg0 = 0.f, c_reg1 = 0.f;
    if (tid >= 128) {
        c_reg0 = c0[b_u * HH + jbase + jj0];
        c_reg1 = c0[b_u * HH + jbase + jj0 + 2];
    }

    fence_proxy_async_cta();
    __syncthreads();

    // prologue: issue step-0 copies (h0 preloaded by init_state, no wait)
    if (tid == 128) {
        #pragma unroll
        for (int ch = 0; ch < 4; ++ch) {
            mbar_expect_tx(mbar0 + 8 * ch, 16384u);
            bulk_g2s(hs_b + (uint32_t)ch * 16384u,
                     (const char*)g_hh[0] + ch * 16384, 16384u, mbar0 + 8 * ch);
        }
    }

    // mma-warp constants (warps 0-3)
    const uint32_t aH = ws_b + (uint32_t)((lane & 15) * W_PITCH + (lane >> 4) * 16);
    const uint32_t aL = aH + 16640u;
    const int r16  = (lane & 7) + 8 * ((lane >> 3) & 1);
    const int bch0 = wid * 2 + (lane >> 4);
    const uint32_t bB = hs_b + (uint32_t)(r16 * 128 + ((bch0 ^ (lane & 7)) * 16));
    const int rloc = lane >> 2;
    const int bcol = wid * 16 + 2 * (lane & 3);
    const int gA = (rloc >> 2) * 512 + jbase + (rloc & 3);
    const int gB = ((rloc + 8) >> 2) * 512 + jbase + ((rloc + 8) & 3);

    for (int s = 0; s < TT; ++s) {
        const int t    = TT - 1 - s;
        const int buf  = s & 1;
        const uint32_t ph = (uint32_t)((s >> 1) & 1);
        const uint32_t mb = mbar0 + (uint32_t)buf * 32u;
        const uint32_t hb = (uint32_t)buf * 65536u;

        if (wid < 4) {
            // seed D fragments from x_proj (overlaps copy latency)
            float d0[4], d1[4];
            const float* xp = g_xp + (size_t)t * (G4 * BB);
            float2 v;
            v = *(const float2*)(xp + (size_t)gA * 64 + bcol);     d0[0] = v.x; d0[1] = v.y;
            v = *(const float2*)(xp + (size_t)gB * 64 + bcol);     d0[2] = v.x; d0[3] = v.y;
            v = *(const float2*)(xp + (size_t)gA * 64 + bcol + 8); d1[0] = v.x; d1[1] = v.y;
            v = *(const float2*)(xp + (size_t)gB * 64 + bcol + 8); d1[2] = v.x; d1[3] = v.y;

            #pragma unroll
            for (int ch = 0; ch < 4; ++ch) {
                mbar_wait(mb + 8u * ch, ph);
                #pragma unroll
                for (int kk = 0; kk < 8; ++kk) {
                    const int ks = ch * 8 + kk;
                    uint32_t ah[4], al[4], bb[4];
                    ldsm4 (ah, aH + (uint32_t)(ks * 32));
                    ldsm4 (al, aL + (uint32_t)(ks * 32));
                    ldsm4t(bb, bB + hb + (uint32_t)(ks * 2048));
                    mma16816f(d0, ah, &bb[0]);
                    mma16816f(d0, al, &bb[0]);
                    mma16816f(d1, ah, &bb[2]);
                    mma16816f(d1, al, &bb[2]);
                }
            }

            *(float2*)&gsh[ rloc      * 64 + bcol]     = make_float2(d0[0], d0[1]);
            *(float2*)&gsh[(rloc + 8) * 64 + bcol]     = make_float2(d0[2], d0[3]);
            *(float2*)&gsh[ rloc      * 64 + bcol + 8] = make_float2(d1[0], d1[1]);
            *(float2*)&gsh[(rloc + 8) * 64 + bcol + 8] = make_float2(d1[2], d1[3]);
        }
        __syncthreads();   // A: gates ready

        if (tid >= 128) {
            __half* hdst = g_hh[(s + 1) & 1];
            #pragma unroll
            for (int e = 0; e < 2; ++e) {
                const int jj = jj0 + e * 2;
                float gi = gsh[( 0 + jj) * 64 + b_u];
                float gf = gsh[( 4 + jj) * 64 + b_u];
                float gg = gsh[( 8 + jj) * 64 + b_u];
                float go = gsh[(12 + jj) * 64 + b_u];
                float ig = sigf(gi), fg = sigf(gf), og = sigf(go);
                float& cr = e ? c_reg1 : c_reg0;
                cr = fg * cr + ig * tanh_fast(gg);
                float hn = og * tanh_fast(cr);
                const int jg = jbase + jj;
                *(__half*)((char*)hdst + h_swz(jg, b_u)) = __float2half_rn(hn);
                out[(size_t)t * (BB * HH) + (size_t)b_u * HH + jg] = hn;
                if (s == TT - 1) {
                    out[(size_t)TT * (BB * HH) + (size_t)b_u * HH + jg]           = hn;
                    out[(size_t)TT * (BB * HH) + BB * HH + (size_t)b_u * HH + jg] = cr;
                }
            }
        }
        __syncthreads();   // B: h written, gsh consumed

        if (tid == 128) {
            red_release(&g_cnt[cta >> 5]);            // announce our 4 rows
            if (s + 1 < TT) {
                const int ns    = s + 1;
                const int nbuf  = ns & 1;
                const unsigned tgt = 32u * (unsigned)ns;
                const uint32_t nmb = mbar0 + (uint32_t)nbuf * 32u;
                const char* src = (const char*)g_hh[nbuf];
                fence_proxy_async_cta();
                #pragma unroll
                for (int ch = 0; ch < 4; ++ch) {
                    while (ld_acq(&g_cnt[ch]) < tgt) { }
                    mbar_expect_tx(nmb + 8u * ch, 16384u);
                    bulk_g2s(hs_b + (uint32_t)nbuf * 65536u + (uint32_t)ch * 16384u,
                             src + ch * 16384, 16384u, nmb + 8u * ch);
                }
            }
        }
    }
}

// ---------------------------------------------------------------------------
// Launch
// ---------------------------------------------------------------------------
extern "C" void kernel_launch(void* const* d_in, const int* in_sizes, int n_in,
                              void* d_out, int out_size)
{
    (void)in_sizes; (void)n_in; (void)out_size;
    const float* input = (const float*)d_in[0];
    const float* h0    = (const float*)d_in[1];
    const float* c0    = (const float*)d_in[2];
    const float* W_ih  = (const float*)d_in[3];
    const float* W_hh  = (const float*)d_in[4];
    const float* b_ih  = (const float*)d_in[5];
    const float* b_hh  = (const float*)d_in[6];
    float* out = (float*)d_out;

    cudaFuncSetAttribute(lstm_recurrent,
                         cudaFuncAttributeMaxDynamicSharedMemorySize, SM_TOT3);
    cudaFuncSetAttribute(xproj_mma,
                         cudaFuncAttributeMaxDynamicSharedMemorySize, SMEM_A_TOT);

    init_state<<<128, 256>>>(h0);
    convert_split<<<1024, 256>>>(input, W_ih);

    dim3 ggrid(G4 / 128, (TT * BB) / 128);   // (16, 256)
    xproj_mma<<<ggrid, 256, SMEM_A_TOT>>>(b_ih, b_hh);

    lstm_recurrent<<<NCTA, 256, SM_TOT3>>>(W_hh, c0, out);
}